// round 11
// baseline (speedup 1.0000x reference)
#include <cuda_runtime.h>
#include <cuda_bf16.h>
#include <cstdint>

#define BB 4
#define TT 4096
#define EE 2048
#define DD 128
#define KTOP 409
#define NCAND 32
#define NKV 4   // split-K slices for gather GEMM

// ---------------- scratch (device globals) ----------------
__device__ float g_q[(size_t)BB * TT * DD];
__device__ float g_norm[BB * TT];
__device__ int   g_topidx[BB * KTOP];
__device__ int   g_nsel[BB];
__device__ int   g_ncand[BB];
__device__ int   g_band[BB][NCAND];
__device__ float g_ktop[BB * KTOP * DD];
__device__ float g_vtop[BB * KTOP * DD];
__device__ float g_part[(size_t)NKV * 2 * BB * KTOP * DD];
// W transposed + split into 2 bf16 limbs: [mat][limb][n(128)][k(2048)]
__device__ __nv_bfloat16 g_wt[3][2][DD][EE];

// ---------------- helpers ----------------
__device__ __forceinline__ uint32_t smem_u32(const void* p) {
    uint32_t a;
    asm("{ .reg .u64 t; cvta.to.shared.u64 t, %1; cvt.u32.u64 %0, t; }"
        : "=r"(a) : "l"(p));
    return a;
}
__device__ __forceinline__ void ldsm4(uint32_t* r, uint32_t addr) {
    asm volatile("ldmatrix.sync.aligned.m8n8.x4.shared.b16 {%0,%1,%2,%3}, [%4];"
                 : "=r"(r[0]), "=r"(r[1]), "=r"(r[2]), "=r"(r[3]) : "r"(addr));
}
__device__ __forceinline__ void mma16816(float* c, const uint32_t* a,
                                         const uint32_t* b) {
    asm volatile(
        "mma.sync.aligned.m16n8k16.row.col.f32.bf16.bf16.f32 "
        "{%0,%1,%2,%3}, {%4,%5,%6,%7}, {%8,%9}, {%0,%1,%2,%3};"
        : "+f"(c[0]), "+f"(c[1]), "+f"(c[2]), "+f"(c[3])
        : "r"(a[0]), "r"(a[1]), "r"(a[2]), "r"(a[3]), "r"(b[0]), "r"(b[1]));
}
__device__ __forceinline__ void sts64(uint32_t a, uint32_t lo, uint32_t hi) {
    asm volatile("st.shared.v2.b32 [%0], {%1,%2};" :: "r"(a), "r"(lo), "r"(hi));
}
__device__ __forceinline__ uint32_t pack_bf16x2(__nv_bfloat162 v) {
    return *reinterpret_cast<uint32_t*>(&v);
}
__device__ __forceinline__ void cp_async16(uint32_t dst, const void* src) {
    asm volatile("cp.async.cg.shared.global [%0], [%1], 16;"
                 :: "r"(dst), "l"(src));
}
__device__ __forceinline__ void cp_commit() {
    asm volatile("cp.async.commit_group;" ::: "memory");
}
__device__ __forceinline__ void cp_wait0() {
    asm volatile("cp.async.wait_group 0;" ::: "memory");
}
__device__ __forceinline__ void cp_wait1() {
    asm volatile("cp.async.wait_group 1;" ::: "memory");
}
__device__ __forceinline__ void bar_sync(int id) {
    asm volatile("bar.sync %0, 512;" :: "r"(id) : "memory");
}
__device__ __forceinline__ void bar_arrive(int id) {
    asm volatile("bar.arrive %0, 512;" :: "r"(id) : "memory");
}

// ---------------- geometry ----------------
constexpr int BK = 32;
constexpr int NCH = EE / BK;      // 64 chunks (full depth)
constexpr int LDAB = 80;          // smem row stride bytes (conflict-free ldmatrix)
constexpr int AB = 128 * LDAB;    // 10240 bytes per limb buffer
constexpr int NSTG = 4;           // pipeline stages
constexpr uint32_t STAGE = 4 * AB;          // Ah, Am, Wh, Wm per stage
constexpr uint32_t S_TOTAL = NSTG * STAGE;  // 163840
#define B_FULL 1
#define B_EMPTY 5

// ---------------- zero output ----------------
__global__ void zero_kernel(float4* o, int n4) {
    for (int i = blockIdx.x * blockDim.x + threadIdx.x; i < n4;
         i += gridDim.x * blockDim.x)
        o[i] = make_float4(0.f, 0.f, 0.f, 0.f);
}

// ---------------- W prep: transpose + 2-limb bf16 split ----------------
__global__ void wprep_kernel(const float* __restrict__ Wq,
                             const float* __restrict__ Wk,
                             const float* __restrict__ Wv) {
    __shared__ float t[32][33];
    const int tid = threadIdx.x;
    const int bk = blockIdx.x * 32, bn = blockIdx.y * 32;
    const float* Ws[3] = {Wq, Wk, Wv};
    for (int m = 0; m < 3; m++) {
        const float* W = Ws[m];
#pragma unroll
        for (int p = 0; p < 4; p++) {
            int i = p * 8 + (tid >> 5), j = tid & 31;
            t[i][j] = W[(bk + i) * DD + bn + j];
        }
        __syncthreads();
#pragma unroll
        for (int p = 0; p < 4; p++) {
            int j = p * 8 + (tid >> 5), i = tid & 31;
            float x = t[i][j];
            __nv_bfloat16 h = __float2bfloat16_rn(x);
            float r1 = x - __bfloat162float(h);
            __nv_bfloat16 md = __float2bfloat16_rn(r1);
            int n = bn + j, k = bk + i;
            g_wt[m][0][n][k] = h;
            g_wt[m][1][n][k] = md;
        }
        __syncthreads();
    }
}

// ---------------- tiny init (keeps gemm at launch #4 for profiling) --------
__global__ void init_sel() {
    if (threadIdx.x < BB) {
        g_nsel[threadIdx.x] = 0;
        g_ncand[threadIdx.x] = 0;
    }
}

// ---------------- A limb conversion + STS ----------------
__device__ __forceinline__ void conv_store(uint32_t base, uint32_t off, float4 v) {
    __nv_bfloat162 h0 = __float22bfloat162_rn(make_float2(v.x, v.y));
    __nv_bfloat162 h1 = __float22bfloat162_rn(make_float2(v.z, v.w));
    float2 hf0 = __bfloat1622float2(h0), hf1 = __bfloat1622float2(h1);
    __nv_bfloat162 m0 =
        __float22bfloat162_rn(make_float2(v.x - hf0.x, v.y - hf0.y));
    __nv_bfloat162 m1 =
        __float22bfloat162_rn(make_float2(v.z - hf1.x, v.w - hf1.y));
    sts64(base + off, pack_bf16x2(h0), pack_bf16x2(h1));
    sts64(base + AB + off, pack_bf16x2(m0), pack_bf16x2(m1));
}

// ---------------- warp-specialized mma.sync split-bf16 GEMM ----------------
// 512 threads: warps 0-7 consumers (ldsm+mma), warps 8-15 producers.
// Producer pipelines cp.async one chunk ahead (wait_group 1) and prefetches
// A two chunks ahead in registers.
template <bool GATHER>
__global__ __launch_bounds__(512, 1) void gemm_mma(const float* __restrict__ A) {
    extern __shared__ char smem[];
    __shared__ float npart[2][128];
    const uint32_t sb = smem_u32(smem);
    const int tid = threadIdx.x, wid = tid >> 5, lane = tid & 31;
    const bool isProd = (tid >= 256);
    const int ptid = tid & 255;

    int b = 0, tile, mat = 0, kbase = 0, nch = NCH;
    const __nv_bfloat16* wt;
    float* part = nullptr;
    if (GATHER) {
        b = blockIdx.x >> 2;
        tile = blockIdx.x & 3;
        mat = blockIdx.y;
        kbase = blockIdx.z * (EE / NKV);
        nch = (EE / NKV) / BK;   // 16
        wt = &g_wt[1 + mat][0][0][0];
        part = g_part + (size_t)(blockIdx.z * 2 + mat) * (BB * KTOP * DD);
    } else {
        tile = blockIdx.x;
        wt = &g_wt[0][0][0][0];
    }

    if (isProd) {
        // ================= PRODUCER =================
        uint32_t aoffg[4], asm_[4];
#pragma unroll
        for (int i = 0; i < 4; i++) {
            int idx = ptid + 256 * i;
            int r = idx >> 3, kc = (idx & 7) * 4;
            int gr;
            if (GATHER) {
                int rl = tile * 128 + r;
                if (rl >= KTOP) rl = KTOP - 1;
                gr = b * TT + g_topidx[b * KTOP + rl];
            } else {
                gr = tile * 128 + r;
            }
            aoffg[i] = (uint32_t)gr * EE + kbase + kc;
            asm_[i] = r * LDAB + kc * 2;
        }
        uint32_t woffg[4], wsm[4];
#pragma unroll
        for (int j = 0; j < 4; j++) {
            int idx = ptid + 256 * j;
            int limb = idx >> 9, rem = idx & 511;
            int n = rem >> 2, kq = (rem & 3) * 8;
            woffg[j] = (uint32_t)limb * DD * EE + (uint32_t)n * EE + kbase + kq;
            wsm[j] = 2 * AB + limb * AB + n * LDAB + kq * 2;
        }

        float4 av0[4], av1[4];
#pragma unroll
        for (int i = 0; i < 4; i++) av0[i] = *(const float4*)(A + aoffg[i]);

        // prologue: issue chunk 0 W
        bar_sync(B_EMPTY + 0);
#pragma unroll
        for (int j = 0; j < 4; j++)
            cp_async16(sb + wsm[j], wt + woffg[j]);
        cp_commit();
        if (nch > 1) {
#pragma unroll
            for (int i = 0; i < 4; i++)
                av1[i] = *(const float4*)(A + aoffg[i] + BK);
        }

        for (int it = 0; it < nch; ++it) {
            const int s = it & (NSTG - 1);
            const uint32_t base = sb + s * STAGE;
            // issue next chunk's W one stage ahead
            if (it + 1 < nch) {
                const int sn = (it + 1) & (NSTG - 1);
                const uint32_t nbase = sb + sn * STAGE;
                bar_sync(B_EMPTY + sn);
                const int kb = (it + 1) * BK;
#pragma unroll
                for (int j = 0; j < 4; j++)
                    cp_async16(nbase + wsm[j], wt + woffg[j] + kb);
                cp_commit();
            }
            // convert current A chunk into stage s, prefetch it+2
            if (it & 1) {
#pragma unroll
                for (int i = 0; i < 4; i++) conv_store(base, asm_[i], av1[i]);
                if (it + 2 < nch) {
                    const int kn = (it + 2) * BK;
#pragma unroll
                    for (int i = 0; i < 4; i++)
                        av1[i] = *(const float4*)(A + aoffg[i] + kn);
                }
            } else {
#pragma unroll
                for (int i = 0; i < 4; i++) conv_store(base, asm_[i], av0[i]);
                if (it + 2 < nch) {
                    const int kn = (it + 2) * BK;
#pragma unroll
                    for (int i = 0; i < 4; i++)
                        av0[i] = *(const float4*)(A + aoffg[i] + kn);
                }
            }
            // retire chunk it's cp.async group (it+1 stays in flight)
            if (it + 1 < nch) cp_wait1(); else cp_wait0();
            __threadfence_block();
            bar_arrive(B_FULL + s);
        }
    } else {
        // ================= CONSUMER =================
        const int wr = wid >> 1, wc = wid & 1;
        const int row0 = wr * 32, n0 = wc * 64;
        uint32_t aoff[2], boff[4];
#pragma unroll
        for (int mt = 0; mt < 2; mt++)
            aoff[mt] = (row0 + mt * 16 + (lane & 15)) * LDAB + (lane >> 4) * 16;
#pragma unroll
        for (int np = 0; np < 4; np++) {
            int nl = n0 + np * 16 + (lane & 7) + ((lane >> 4) & 1) * 8;
            boff[np] = nl * LDAB + (lane & 8) * 2;
        }

        float c[2][8][4];
#pragma unroll
        for (int mt = 0; mt < 2; mt++)
#pragma unroll
            for (int nt = 0; nt < 8; nt++)
#pragma unroll
                for (int u = 0; u < 4; u++) c[mt][nt][u] = 0.f;

#pragma unroll
        for (int s = 0; s < NSTG; s++) bar_arrive(B_EMPTY + s);

        for (int it = 0; it < nch; ++it) {
            const int s = it & (NSTG - 1);
            const uint32_t base = sb + s * STAGE;
            bar_sync(B_FULL + s);
#pragma unroll
            for (int kk = 0; kk < 2; kk++) {
                uint32_t ah[2][4], am[2][4];
#pragma unroll
                for (int mt = 0; mt < 2; mt++) {
                    ldsm4(ah[mt], base + aoff[mt] + kk * 32);
                    ldsm4(am[mt], base + AB + aoff[mt] + kk * 32);
                }
#pragma unroll
                for (int np = 0; np < 4; np++) {
                    uint32_t bh[4], bm[4];
                    ldsm4(bh, base + 2 * AB + boff[np] + kk * 32);
                    ldsm4(bm, base + 3 * AB + boff[np] + kk * 32);
#pragma unroll
                    for (int mt = 0; mt < 2; mt++) {
                        mma16816(c[mt][2 * np], ah[mt], bh);
                        mma16816(c[mt][2 * np], ah[mt], bm);
                        mma16816(c[mt][2 * np], am[mt], bh);
                        mma16816(c[mt][2 * np + 1], ah[mt], bh + 2);
                        mma16816(c[mt][2 * np + 1], ah[mt], bm + 2);
                        mma16816(c[mt][2 * np + 1], am[mt], bh + 2);
                    }
                }
            }
            bar_arrive(B_EMPTY + s);
        }

        // -------- epilogue --------
        if (!GATHER) {
#pragma unroll
            for (int mt = 0; mt < 2; mt++) {
                float slo = 0.f, shi = 0.f;
#pragma unroll
                for (int nt = 0; nt < 8; nt++) {
                    slo += c[mt][nt][0] * c[mt][nt][0] +
                           c[mt][nt][1] * c[mt][nt][1];
                    shi += c[mt][nt][2] * c[mt][nt][2] +
                           c[mt][nt][3] * c[mt][nt][3];
                }
                slo += __shfl_xor_sync(0xffffffffu, slo, 1);
                slo += __shfl_xor_sync(0xffffffffu, slo, 2);
                shi += __shfl_xor_sync(0xffffffffu, shi, 1);
                shi += __shfl_xor_sync(0xffffffffu, shi, 2);
                if ((lane & 3) == 0) {
                    int rl = row0 + mt * 16 + (lane >> 2);
                    npart[wc][rl] = slo;
                    npart[wc][rl + 8] = shi;
                }
            }
        }

#pragma unroll
        for (int mt = 0; mt < 2; mt++) {
            int rl = row0 + mt * 16 + (lane >> 2);
#pragma unroll
            for (int nt = 0; nt < 8; nt++) {
                int col = n0 + nt * 8 + (lane & 3) * 2;
                if (!GATHER) {
                    float* p0 = g_q + (size_t)(tile * 128 + rl) * DD + col;
                    *(float2*)p0 = make_float2(c[mt][nt][0], c[mt][nt][1]);
                    *(float2*)(p0 + 8 * DD) =
                        make_float2(c[mt][nt][2], c[mt][nt][3]);
                } else {
                    int r0g = tile * 128 + rl;
                    if (r0g < KTOP) {
                        float* p0 = part + ((size_t)b * KTOP + r0g) * DD + col;
                        *(float2*)p0 = make_float2(c[mt][nt][0], c[mt][nt][1]);
                    }
                    if (r0g + 8 < KTOP) {
                        float* p1 =
                            part + ((size_t)b * KTOP + r0g + 8) * DD + col;
                        *(float2*)p1 = make_float2(c[mt][nt][2], c[mt][nt][3]);
                    }
                }
            }
        }
    }

    if (!GATHER) {
        __syncthreads();
        if (tid < 128)
            g_norm[tile * 128 + tid] = npart[0][tid] + npart[1][tid];
    }
}

// ---------------- split-K reduction for k/v ----------------
__global__ void reduce_kv() {
    const int n = BB * KTOP * DD;
    for (int idx = blockIdx.x * blockDim.x + threadIdx.x; idx < 2 * n;
         idx += gridDim.x * blockDim.x) {
        int mat = (idx >= n) ? 1 : 0;
        int off = mat ? idx - n : idx;
        float s = 0.f;
#pragma unroll
        for (int z = 0; z < NKV; z++)
            s += g_part[(size_t)(z * 2 + mat) * n + off];
        (mat ? g_vtop : g_ktop)[off] = s;
    }
}

// ---------------- set-based top-k: binary search on norm bits ----------------
__global__ __launch_bounds__(1024) void topk_select() {
    const int b = blockIdx.x, tid = threadIdx.x;
    const int lane = tid & 31, w = tid >> 5;
    __shared__ int wsum[32];
    __shared__ int s_tot;
    __shared__ int s_cand;

    uint32_t bits[4];
#pragma unroll
    for (int i = 0; i < 4; i++)
        bits[i] = __float_as_uint(g_norm[b * TT + tid + i * 1024]);
    if (tid == 0) s_cand = 0;

    uint32_t lo = 0, hi = 0xFFFFFFFFu;
    for (int step = 0; step < 32; ++step) {
        uint32_t mid = lo + ((hi - lo) >> 1);
        int cctr = (bits[0] >= mid) + (bits[1] >= mid) + (bits[2] >= mid) +
                   (bits[3] >= mid);
#pragma unroll
        for (int o = 16; o; o >>= 1) cctr += __shfl_xor_sync(0xffffffffu, cctr, o);
        if (lane == 0) wsum[w] = cctr;
        __syncthreads();
        if (tid < 32) {
            int s = wsum[tid];
#pragma unroll
            for (int o = 16; o; o >>= 1) s += __shfl_xor_sync(0xffffffffu, s, o);
            if (tid == 0) s_tot = s;
        }
        __syncthreads();
        if (s_tot >= KTOP) lo = mid; else hi = mid;
        __syncthreads();
    }
    const float thrv = __uint_as_float(lo);
    const uint32_t bhi = __float_as_uint(thrv * (1.f + 4e-5f));
    const uint32_t blo = __float_as_uint(thrv * (1.f - 4e-5f));

    int f[4], myc = 0;
#pragma unroll
    for (int i = 0; i < 4; i++) {
        f[i] = (bits[i] > bhi);
        myc += f[i];
    }
    int incl = myc;
#pragma unroll
    for (int o = 1; o < 32; o <<= 1) {
        int nvv = __shfl_up_sync(0xffffffffu, incl, o);
        if (lane >= o) incl += nvv;
    }
    if (lane == 31) wsum[w] = incl;
    __syncthreads();
    if (tid < 32) {
        int v2 = wsum[tid];
        int inc2 = v2;
#pragma unroll
        for (int o = 1; o < 32; o <<= 1) {
            int nvv = __shfl_up_sync(0xffffffffu, inc2, o);
            if (tid >= o) inc2 += nvv;
        }
        wsum[tid] = inc2 - v2;
        if (tid == 31) s_tot = inc2;
    }
    __syncthreads();
    int pos = wsum[w] + (incl - myc);
#pragma unroll
    for (int i = 0; i < 4; i++) {
        if (f[i]) g_topidx[b * KTOP + pos++] = tid + i * 1024;
    }
    if (tid == 0) g_nsel[b] = s_tot;

#pragma unroll
    for (int i = 0; i < 4; i++) {
        if (bits[i] >= blo && bits[i] <= bhi) {
            int slot = atomicAdd(&s_cand, 1);
            if (slot < NCAND) g_band[b][slot] = tid + i * 1024;
        }
    }
    __syncthreads();
    if (tid == 0) g_ncand[b] = (s_cand < NCAND) ? s_cand : NCAND;
}

// ---------------- finalize: exact norms for candidates + ranking ----------
// One block per batch; computes exact fp32 q-norms for the (few) band rows
// and writes the final KTOP-C1 topidx slots. No q gather (attn reads g_q).
__global__ __launch_bounds__(1024) void finalize_kernel(
    const float* __restrict__ A, const float* __restrict__ Wq) {
    const int b = blockIdx.x, tid = threadIdx.x;
    __shared__ float qpart[8][128];
    __shared__ float red[128];
    __shared__ float bnorm[NCAND];
    __shared__ unsigned long long bkey[NCAND];
    const int C1 = g_nsel[b];
    const int nc = g_ncand[b];
    const int remaining = KTOP - C1;
    const int s = tid >> 7, n = tid & 127;

    for (int c = 0; c < nc; ++c) {
        const int row = g_band[b][c];
        const float* x = A + ((size_t)b * TT + row) * EE + s * 256;
        const float* wp = Wq + (size_t)(s * 256) * DD + n;
        float a0 = 0.f, a1 = 0.f, a2 = 0.f, a3 = 0.f;
#pragma unroll 2
        for (int k = 0; k < 256; k += 4) {
            a0 += x[k] * wp[(size_t)k * DD];
            a1 += x[k + 1] * wp[(size_t)(k + 1) * DD];
            a2 += x[k + 2] * wp[(size_t)(k + 2) * DD];
            a3 += x[k + 3] * wp[(size_t)(k + 3) * DD];
        }
        qpart[s][n] = (a0 + a1) + (a2 + a3);
        __syncthreads();
        if (tid < 128) {
            float q = 0.f;
#pragma unroll
            for (int ss = 0; ss < 8; ss++) q += qpart[ss][tid];
            red[tid] = q * q;
        }
        __syncthreads();
        for (int o = 64; o > 0; o >>= 1) {
            if (tid < o) red[tid] += red[tid + o];
            __syncthreads();
        }
        if (tid == 0) bnorm[c] = red[0];
        __syncthreads();
    }

    if (tid < nc) {
        int r = g_band[b][tid];
        unsigned nb = __float_as_uint(bnorm[tid]);
        bkey[tid] = ((unsigned long long)nb << 32) | (unsigned)(0xFFFFFFFFu - r);
    }
    __syncthreads();
    if (tid < nc) {
        unsigned long long me = bkey[tid];
        int rank = 0;
        for (int t = 0; t < nc; t++) rank += (bkey[t] > me);
        if (rank < remaining) {
            int r = (int)(0xFFFFFFFFu - (unsigned)(me & 0xFFFFFFFFull));
            g_topidx[b * KTOP + C1 + rank] = r;
        }
    }
}

// ---------------- attention on the top-k set, scattered store ----------------
__global__ __launch_bounds__(256) void attn_kernel(float* __restrict__ out) {
    constexpr int QT = 16;
    constexpr int NT = 26;
    constexpr int CW = 416;
    __shared__ float q_s[QT][132];
    __shared__ float kv_s[QT][132];
    __shared__ float S_s[QT][CW];
    __shared__ int qidx[QT];

    const int b = blockIdx.x / NT;
    const int qt = blockIdx.x % NT;
    const int q0 = qt * QT;
    const int tid = threadIdx.x;
    const float scale = 0.08838834764831845f;

    if (tid < QT) {
        int r = q0 + tid;
        qidx[tid] = (r < KTOP) ? g_topidx[b * KTOP + r] : -1;
    }
    __syncthreads();
    for (int u = tid; u < QT * DD; u += 256) {
        int i = u >> 7, d = u & 127;
        int rg = qidx[i];
        q_s[i][d] = (rg >= 0) ? g_q[((size_t)b * TT + rg) * DD + d] : 0.f;
    }

    const int i = tid >> 4;
    const int jj = tid & 15;

    for (int jt = 0; jt < NT; jt++) {
        __syncthreads();
        for (int u = tid; u < QT * DD; u += 256) {
            int j2 = u >> 7, d = u & 127;
            int j = jt * QT + j2;
            kv_s[j2][d] = (j < KTOP) ? g_ktop[((size_t)b * KTOP + j) * DD + d] : 0.f;
        }
        __syncthreads();
        float s = 0.f;
#pragma unroll
        for (int d4 = 0; d4 < DD; d4 += 4) {
            float4 qa = *(const float4*)&q_s[i][d4];
            float4 kb = *(const float4*)&kv_s[jj][d4];
            s += qa.x * kb.x + qa.y * kb.y + qa.z * kb.z + qa.w * kb.w;
        }
        int j = jt * QT + jj;
        S_s[i][j] = (j < KTOP) ? s * scale : -1e30f;
    }
    __syncthreads();

    {
        int l = tid & 15;
        float m = -1e30f;
        for (int cc = l; cc < CW; cc += 16) m = fmaxf(m, S_s[i][cc]);
#pragma unroll
        for (int o = 8; o; o >>= 1) m = fmaxf(m, __shfl_xor_sync(0xffffffffu, m, o));
        float sum = 0.f;
        for (int cc = l; cc < CW; cc += 16) {
            float e = __expf(S_s[i][cc] - m);
            S_s[i][cc] = e;
            sum += e;
        }
#pragma unroll
        for (int o = 8; o; o >>= 1) sum += __shfl_xor_sync(0xffffffffu, sum, o);
        float inv = 1.f / sum;
        for (int cc = l; cc < CW; cc += 16) S_s[i][cc] *= inv;
    }

    float acc[8] = {0.f, 0.f, 0.f, 0.f, 0.f, 0.f, 0.f, 0.f};
    const int d0 = (tid & 15) * 8;
    for (int jt = 0; jt < NT; jt++) {
        __syncthreads();
        for (int u = tid; u < QT * DD; u += 256) {
            int j2 = u >> 7, d = u & 127;
            int j = jt * QT + j2;
            kv_s[j2][d] = (j < KTOP) ? g_vtop[((size_t)b * KTOP + j) * DD + d] : 0.f;
        }
        __syncthreads();
#pragma unroll
        for (int j2 = 0; j2 < QT; j2++) {
            float p = S_s[i][jt * QT + j2];
            float4 v0 = *(const float4*)&kv_s[j2][d0];
            float4 v1 = *(const float4*)&kv_s[j2][d0 + 4];
            acc[0] += p * v0.x;
            acc[1] += p * v0.y;
            acc[2] += p * v0.z;
            acc[3] += p * v0.w;
            acc[4] += p * v1.x;
            acc[5] += p * v1.y;
            acc[6] += p * v1.z;
            acc[7] += p * v1.w;
        }
    }
    int r = q0 + i;
    if (r < KTOP) {
        int rg = g_topidx[b * KTOP + r];
        float* op = out + ((size_t)b * TT + rg) * DD + d0;
        *(float4*)op = make_float4(acc[0], acc[1], acc[2], acc[3]);
        *(float4*)(op + 4) = make_float4(acc[4], acc[5], acc[6], acc[7]);
    }
}

// ---------------- launch ----------------
extern "C" void kernel_launch(void* const* d_in, const int* in_sizes, int n_in,
                              void* d_out, int out_size) {
    (void)in_sizes;
    (void)n_in;
    (void)out_size;
    const float* index = (const float*)d_in[0];
    const float* Wq = (const float*)d_in[1];
    const float* Wk = (const float*)d_in[2];
    const float* Wv = (const float*)d_in[3];
    float* out = (float*)d_out;

    cudaFuncSetAttribute(gemm_mma<false>,
                         cudaFuncAttributeMaxDynamicSharedMemorySize, S_TOTAL);
    cudaFuncSetAttribute(gemm_mma<true>,
                         cudaFuncAttributeMaxDynamicSharedMemorySize, S_TOTAL);

    zero_kernel<<<512, 256>>>((float4*)out, BB * TT * DD / 4);          // 1
    wprep_kernel<<<dim3(EE / 32, DD / 32), 256>>>(Wq, Wk, Wv);          // 2
    init_sel<<<1, 32>>>();                                              // 3
    gemm_mma<false><<<(BB * TT) / 128, 512, S_TOTAL>>>(index);          // 4 (profiled)
    topk_select<<<BB, 1024>>>();                                        // 5
    finalize_kernel<<<BB, 1024>>>(index, Wq);                           // 6
    gemm_mma<true><<<dim3(16, 2, NKV), 512, S_TOTAL>>>(index);          // 7
    reduce_kv<<<512, 256>>>();                                          // 8
    attn_kernel<<<BB * 26, 256>>>(out);                                 // 9
}

// round 12
// speedup vs baseline: 1.1721x; 1.1721x over previous
#include <cuda_runtime.h>
#include <cuda_bf16.h>
#include <cstdint>

#define BB 4
#define TT 4096
#define EE 2048
#define DD 128
#define KTOP 409
#define NCAND 32
#define NKV 4   // split-K slices for gather GEMM

// ---------------- scratch (device globals) ----------------
__device__ float g_q[(size_t)BB * TT * DD];
__device__ float g_norm[BB * TT];
__device__ int   g_topidx[BB * KTOP];
__device__ int   g_nsel[BB];
__device__ int   g_ncand[BB];
__device__ int   g_band[BB][NCAND];
__device__ float g_bnorm[BB][NCAND];
__device__ float g_ktop[BB * KTOP * DD];
__device__ float g_vtop[BB * KTOP * DD];
__device__ float g_part[(size_t)NKV * 2 * BB * KTOP * DD];
// W transposed + split into 2 bf16 limbs: [mat][limb][n(128)][k(2048)]
__device__ __nv_bfloat16 g_wt[3][2][DD][EE];

// ---------------- helpers ----------------
__device__ __forceinline__ uint32_t smem_u32(const void* p) {
    uint32_t a;
    asm("{ .reg .u64 t; cvta.to.shared.u64 t, %1; cvt.u32.u64 %0, t; }"
        : "=r"(a) : "l"(p));
    return a;
}
__device__ __forceinline__ void ldsm4(uint32_t* r, uint32_t addr) {
    asm volatile("ldmatrix.sync.aligned.m8n8.x4.shared.b16 {%0,%1,%2,%3}, [%4];"
                 : "=r"(r[0]), "=r"(r[1]), "=r"(r[2]), "=r"(r[3]) : "r"(addr));
}
__device__ __forceinline__ void mma16816(float* c, const uint32_t* a,
                                         const uint32_t* b) {
    asm volatile(
        "mma.sync.aligned.m16n8k16.row.col.f32.bf16.bf16.f32 "
        "{%0,%1,%2,%3}, {%4,%5,%6,%7}, {%8,%9}, {%0,%1,%2,%3};"
        : "+f"(c[0]), "+f"(c[1]), "+f"(c[2]), "+f"(c[3])
        : "r"(a[0]), "r"(a[1]), "r"(a[2]), "r"(a[3]), "r"(b[0]), "r"(b[1]));
}
__device__ __forceinline__ void sts64(uint32_t a, uint32_t lo, uint32_t hi) {
    asm volatile("st.shared.v2.b32 [%0], {%1,%2};" :: "r"(a), "r"(lo), "r"(hi));
}
__device__ __forceinline__ uint32_t pack_bf16x2(__nv_bfloat162 v) {
    return *reinterpret_cast<uint32_t*>(&v);
}
__device__ __forceinline__ void cp_async16(uint32_t dst, const void* src) {
    asm volatile("cp.async.cg.shared.global [%0], [%1], 16;"
                 :: "r"(dst), "l"(src));
}
__device__ __forceinline__ void cp_commit() {
    asm volatile("cp.async.commit_group;" ::: "memory");
}
__device__ __forceinline__ void cp_wait0() {
    asm volatile("cp.async.wait_group 0;" ::: "memory");
}
__device__ __forceinline__ void bar_sync(int id) {
    asm volatile("bar.sync %0, 512;" :: "r"(id) : "memory");
}
__device__ __forceinline__ void bar_arrive(int id) {
    asm volatile("bar.arrive %0, 512;" :: "r"(id) : "memory");
}

// ---------------- geometry ----------------
constexpr int BK = 32;
constexpr int NCH = EE / BK;      // 64 chunks (full depth)
constexpr int LDAB = 80;          // smem row stride bytes (conflict-free ldmatrix)
constexpr int AB = 128 * LDAB;    // 10240 bytes per limb buffer
constexpr int NSTG = 4;           // pipeline stages
constexpr uint32_t STAGE = 4 * AB;          // Ah, Am, Wh, Wm per stage
constexpr uint32_t S_TOTAL = NSTG * STAGE;  // 163840
#define B_FULL 1
#define B_EMPTY 5

// ---------------- zero output ----------------
__global__ void zero_kernel(float4* o, int n4) {
    for (int i = blockIdx.x * blockDim.x + threadIdx.x; i < n4;
         i += gridDim.x * blockDim.x)
        o[i] = make_float4(0.f, 0.f, 0.f, 0.f);
}

// ---------------- W prep: transpose + 2-limb bf16 split ----------------
__global__ void wprep_kernel(const float* __restrict__ Wq,
                             const float* __restrict__ Wk,
                             const float* __restrict__ Wv) {
    __shared__ float t[32][33];
    const int tid = threadIdx.x;
    const int bk = blockIdx.x * 32, bn = blockIdx.y * 32;
    const float* Ws[3] = {Wq, Wk, Wv};
    for (int m = 0; m < 3; m++) {
        const float* W = Ws[m];
#pragma unroll
        for (int p = 0; p < 4; p++) {
            int i = p * 8 + (tid >> 5), j = tid & 31;
            t[i][j] = W[(bk + i) * DD + bn + j];
        }
        __syncthreads();
#pragma unroll
        for (int p = 0; p < 4; p++) {
            int j = p * 8 + (tid >> 5), i = tid & 31;
            float x = t[i][j];
            __nv_bfloat16 h = __float2bfloat16_rn(x);
            float r1 = x - __bfloat162float(h);
            __nv_bfloat16 md = __float2bfloat16_rn(r1);
            int n = bn + j, k = bk + i;
            g_wt[m][0][n][k] = h;
            g_wt[m][1][n][k] = md;
        }
        __syncthreads();
    }
}

// ---------------- warp-specialized mma.sync split-bf16 GEMM ----------------
// 512 threads: warps 0-7 consumers (ldsm+mma), warps 8-15 producers
// (cp.async W limbs, load+convert A to 2 bf16 limbs, STS). 4-stage ring.
template <bool GATHER>
__global__ __launch_bounds__(512, 1) void gemm_mma(const float* __restrict__ A) {
    extern __shared__ char smem[];
    __shared__ float npart[2][128];
    const uint32_t sb = smem_u32(smem);
    const int tid = threadIdx.x, wid = tid >> 5, lane = tid & 31;
    const bool isProd = (tid >= 256);
    const int ptid = tid & 255;

    int b = 0, tile, mat = 0, kbase = 0, nch = NCH;
    const __nv_bfloat16* wt;
    float* part = nullptr;
    if (GATHER) {
        b = blockIdx.x >> 2;
        tile = blockIdx.x & 3;
        mat = blockIdx.y;
        kbase = blockIdx.z * (EE / NKV);
        nch = (EE / NKV) / BK;   // 16
        wt = &g_wt[1 + mat][0][0][0];
        part = g_part + (size_t)(blockIdx.z * 2 + mat) * (BB * KTOP * DD);
    } else {
        tile = blockIdx.x;
        wt = &g_wt[0][0][0][0];
    }

    if (isProd) {
        // ================= PRODUCER =================
        uint32_t aoffg[4], asm_[4];
#pragma unroll
        for (int i = 0; i < 4; i++) {
            int idx = ptid + 256 * i;
            int r = idx >> 3, kc = (idx & 7) * 4;
            int gr;
            if (GATHER) {
                int rl = tile * 128 + r;
                if (rl >= KTOP) rl = KTOP - 1;
                gr = b * TT + g_topidx[b * KTOP + rl];
            } else {
                gr = tile * 128 + r;
            }
            aoffg[i] = (uint32_t)gr * EE + kbase + kc;
            asm_[i] = r * LDAB + kc * 2;
        }
        uint32_t woffg[4], wsm[4];
#pragma unroll
        for (int j = 0; j < 4; j++) {
            int idx = ptid + 256 * j;
            int limb = idx >> 9, rem = idx & 511;
            int n = rem >> 2, kq = (rem & 3) * 8;
            woffg[j] = (uint32_t)limb * DD * EE + (uint32_t)n * EE + kbase + kq;
            wsm[j] = 2 * AB + limb * AB + n * LDAB + kq * 2;
        }

        float4 av[4];
#pragma unroll
        for (int i = 0; i < 4; i++) av[i] = *(const float4*)(A + aoffg[i]);

        for (int it = 0; it < nch; ++it) {
            const int s = it & (NSTG - 1);
            const uint32_t base = sb + s * STAGE;
            bar_sync(B_EMPTY + s);
            const int kb = it * BK;
#pragma unroll
            for (int j = 0; j < 4; j++)
                cp_async16(base + wsm[j], wt + woffg[j] + kb);
            cp_commit();
#pragma unroll
            for (int i = 0; i < 4; i++) {
                __nv_bfloat162 h0 =
                    __float22bfloat162_rn(make_float2(av[i].x, av[i].y));
                __nv_bfloat162 h1 =
                    __float22bfloat162_rn(make_float2(av[i].z, av[i].w));
                float2 hf0 = __bfloat1622float2(h0), hf1 = __bfloat1622float2(h1);
                __nv_bfloat162 m0 = __float22bfloat162_rn(
                    make_float2(av[i].x - hf0.x, av[i].y - hf0.y));
                __nv_bfloat162 m1 = __float22bfloat162_rn(
                    make_float2(av[i].z - hf1.x, av[i].w - hf1.y));
                sts64(base + asm_[i], pack_bf16x2(h0), pack_bf16x2(h1));
                sts64(base + AB + asm_[i], pack_bf16x2(m0), pack_bf16x2(m1));
            }
            if (it + 1 < nch) {
                const int kn = (it + 1) * BK;
#pragma unroll
                for (int i = 0; i < 4; i++)
                    av[i] = *(const float4*)(A + aoffg[i] + kn);
            }
            cp_wait0();
            __threadfence_block();
            bar_arrive(B_FULL + s);
        }
    } else {
        // ================= CONSUMER =================
        const int wr = wid >> 1, wc = wid & 1;
        const int row0 = wr * 32, n0 = wc * 64;
        uint32_t aoff[2], boff[4];
#pragma unroll
        for (int mt = 0; mt < 2; mt++)
            aoff[mt] = (row0 + mt * 16 + (lane & 15)) * LDAB + (lane >> 4) * 16;
#pragma unroll
        for (int np = 0; np < 4; np++) {
            int nl = n0 + np * 16 + (lane & 7) + ((lane >> 4) & 1) * 8;
            boff[np] = nl * LDAB + (lane & 8) * 2;
        }

        float c[2][8][4];
#pragma unroll
        for (int mt = 0; mt < 2; mt++)
#pragma unroll
            for (int nt = 0; nt < 8; nt++)
#pragma unroll
                for (int u = 0; u < 4; u++) c[mt][nt][u] = 0.f;

#pragma unroll
        for (int s = 0; s < NSTG; s++) bar_arrive(B_EMPTY + s);

        for (int it = 0; it < nch; ++it) {
            const int s = it & (NSTG - 1);
            const uint32_t base = sb + s * STAGE;
            bar_sync(B_FULL + s);
#pragma unroll
            for (int kk = 0; kk < 2; kk++) {
                uint32_t ah[2][4], am[2][4];
#pragma unroll
                for (int mt = 0; mt < 2; mt++) {
                    ldsm4(ah[mt], base + aoff[mt] + kk * 32);
                    ldsm4(am[mt], base + AB + aoff[mt] + kk * 32);
                }
#pragma unroll
                for (int np = 0; np < 4; np++) {
                    uint32_t bh[4], bm[4];
                    ldsm4(bh, base + 2 * AB + boff[np] + kk * 32);
                    ldsm4(bm, base + 3 * AB + boff[np] + kk * 32);
#pragma unroll
                    for (int mt = 0; mt < 2; mt++) {
                        mma16816(c[mt][2 * np], ah[mt], bh);
                        mma16816(c[mt][2 * np], ah[mt], bm);
                        mma16816(c[mt][2 * np], am[mt], bh);
                        mma16816(c[mt][2 * np + 1], ah[mt], bh + 2);
                        mma16816(c[mt][2 * np + 1], ah[mt], bm + 2);
                        mma16816(c[mt][2 * np + 1], am[mt], bh + 2);
                    }
                }
            }
            bar_arrive(B_EMPTY + s);
        }

        // -------- epilogue --------
        if (!GATHER) {
#pragma unroll
            for (int mt = 0; mt < 2; mt++) {
                float slo = 0.f, shi = 0.f;
#pragma unroll
                for (int nt = 0; nt < 8; nt++) {
                    slo += c[mt][nt][0] * c[mt][nt][0] +
                           c[mt][nt][1] * c[mt][nt][1];
                    shi += c[mt][nt][2] * c[mt][nt][2] +
                           c[mt][nt][3] * c[mt][nt][3];
                }
                slo += __shfl_xor_sync(0xffffffffu, slo, 1);
                slo += __shfl_xor_sync(0xffffffffu, slo, 2);
                shi += __shfl_xor_sync(0xffffffffu, shi, 1);
                shi += __shfl_xor_sync(0xffffffffu, shi, 2);
                if ((lane & 3) == 0) {
                    int rl = row0 + mt * 16 + (lane >> 2);
                    npart[wc][rl] = slo;
                    npart[wc][rl + 8] = shi;
                }
            }
        }

#pragma unroll
        for (int mt = 0; mt < 2; mt++) {
            int rl = row0 + mt * 16 + (lane >> 2);
#pragma unroll
            for (int nt = 0; nt < 8; nt++) {
                int col = n0 + nt * 8 + (lane & 3) * 2;
                if (!GATHER) {
                    float* p0 = g_q + (size_t)(tile * 128 + rl) * DD + col;
                    *(float2*)p0 = make_float2(c[mt][nt][0], c[mt][nt][1]);
                    *(float2*)(p0 + 8 * DD) =
                        make_float2(c[mt][nt][2], c[mt][nt][3]);
                } else {
                    int r0g = tile * 128 + rl;
                    if (r0g < KTOP) {
                        float* p0 = part + ((size_t)b * KTOP + r0g) * DD + col;
                        *(float2*)p0 = make_float2(c[mt][nt][0], c[mt][nt][1]);
                    }
                    if (r0g + 8 < KTOP) {
                        float* p1 =
                            part + ((size_t)b * KTOP + r0g + 8) * DD + col;
                        *(float2*)p1 = make_float2(c[mt][nt][2], c[mt][nt][3]);
                    }
                }
            }
        }
    }

    if (!GATHER) {
        __syncthreads();
        if (tid < 128)
            g_norm[tile * 128 + tid] = npart[0][tid] + npart[1][tid];
    }
}

// ---------------- split-K reduction for k/v ----------------
__global__ void reduce_kv() {
    const int n = BB * KTOP * DD;
    for (int idx = blockIdx.x * blockDim.x + threadIdx.x; idx < 2 * n;
         idx += gridDim.x * blockDim.x) {
        int mat = (idx >= n) ? 1 : 0;
        int off = mat ? idx - n : idx;
        float s = 0.f;
#pragma unroll
        for (int z = 0; z < NKV; z++)
            s += g_part[(size_t)(z * 2 + mat) * n + off];
        (mat ? g_vtop : g_ktop)[off] = s;
    }
}

// ---------------- set-based top-k: binary search on norm bits ----------------
__global__ __launch_bounds__(1024) void topk_select() {
    const int b = blockIdx.x, tid = threadIdx.x;
    const int lane = tid & 31, w = tid >> 5;
    __shared__ int wsum[32];
    __shared__ int s_tot;
    __shared__ int s_cand;

    uint32_t bits[4];
#pragma unroll
    for (int i = 0; i < 4; i++)
        bits[i] = __float_as_uint(g_norm[b * TT + tid + i * 1024]);
    if (tid == 0) s_cand = 0;

    uint32_t lo = 0, hi = 0xFFFFFFFFu;
    for (int step = 0; step < 32; ++step) {
        uint32_t mid = lo + ((hi - lo) >> 1);
        int cctr = (bits[0] >= mid) + (bits[1] >= mid) + (bits[2] >= mid) +
                   (bits[3] >= mid);
#pragma unroll
        for (int o = 16; o; o >>= 1) cctr += __shfl_xor_sync(0xffffffffu, cctr, o);
        if (lane == 0) wsum[w] = cctr;
        __syncthreads();
        if (tid < 32) {
            int s = wsum[tid];
#pragma unroll
            for (int o = 16; o; o >>= 1) s += __shfl_xor_sync(0xffffffffu, s, o);
            if (tid == 0) s_tot = s;
        }
        __syncthreads();
        if (s_tot >= KTOP) lo = mid; else hi = mid;
        __syncthreads();
    }
    const float thrv = __uint_as_float(lo);
    const uint32_t bhi = __float_as_uint(thrv * (1.f + 4e-5f));
    const uint32_t blo = __float_as_uint(thrv * (1.f - 4e-5f));

    int f[4], myc = 0;
#pragma unroll
    for (int i = 0; i < 4; i++) {
        f[i] = (bits[i] > bhi);
        myc += f[i];
    }
    int incl = myc;
#pragma unroll
    for (int o = 1; o < 32; o <<= 1) {
        int nvv = __shfl_up_sync(0xffffffffu, incl, o);
        if (lane >= o) incl += nvv;
    }
    if (lane == 31) wsum[w] = incl;
    __syncthreads();
    if (tid < 32) {
        int v2 = wsum[tid];
        int inc2 = v2;
#pragma unroll
        for (int o = 1; o < 32; o <<= 1) {
            int nvv = __shfl_up_sync(0xffffffffu, inc2, o);
            if (tid >= o) inc2 += nvv;
        }
        wsum[tid] = inc2 - v2;
        if (tid == 31) s_tot = inc2;
    }
    __syncthreads();
    int pos = wsum[w] + (incl - myc);
#pragma unroll
    for (int i = 0; i < 4; i++) {
        if (f[i]) g_topidx[b * KTOP + pos++] = tid + i * 1024;
    }
    if (tid == 0) g_nsel[b] = s_tot;

#pragma unroll
    for (int i = 0; i < 4; i++) {
        if (bits[i] >= blo && bits[i] <= bhi) {
            int slot = atomicAdd(&s_cand, 1);
            if (slot < NCAND) g_band[b][slot] = tid + i * 1024;
        }
    }
    __syncthreads();
    if (tid == 0) g_ncand[b] = (s_cand < NCAND) ? s_cand : NCAND;
}

// ---------------- exact fp32 norms for candidate rows (parallel) ----------
__global__ __launch_bounds__(256) void refine_kernel(const float* __restrict__ A,
                                                     const float* __restrict__ Wq) {
    const int slot = blockIdx.x, b = blockIdx.y;
    if (slot >= g_ncand[b]) return;
    const int n = threadIdx.x & 127, half = threadIdx.x >> 7;
    const int row = g_band[b][slot];
    const float* x = A + ((size_t)b * TT + row) * EE + half * (EE / 2);
    const float* wp = Wq + (size_t)half * (EE / 2) * DD + n;
    float s0 = 0.f, s1 = 0.f, s2 = 0.f, s3 = 0.f;
#pragma unroll 2
    for (int k = 0; k < EE / 2; k += 4) {
        s0 += x[k] * wp[(size_t)k * DD];
        s1 += x[k + 1] * wp[(size_t)(k + 1) * DD];
        s2 += x[k + 2] * wp[(size_t)(k + 2) * DD];
        s3 += x[k + 3] * wp[(size_t)(k + 3) * DD];
    }
    __shared__ float qv[2][128];
    qv[half][n] = (s0 + s1) + (s2 + s3);
    __syncthreads();
    __shared__ float red[128];
    if (threadIdx.x < 128) {
        float q = qv[0][n] + qv[1][n];
        red[n] = q * q;
    }
    __syncthreads();
    for (int o = 64; o > 0; o >>= 1) {
        if (threadIdx.x < o) red[threadIdx.x] += red[threadIdx.x + o];
        __syncthreads();
    }
    if (threadIdx.x == 0) g_bnorm[b][slot] = red[0];
}

// ---------------- finalize: rank candidates exactly ----------
__global__ __launch_bounds__(32) void finalize_kernel() {
    const int b = blockIdx.x, tid = threadIdx.x;
    __shared__ unsigned long long bkey[NCAND];
    const int C1 = g_nsel[b];
    const int nc = g_ncand[b];
    const int remaining = KTOP - C1;
    if (tid < nc) {
        int r = g_band[b][tid];
        unsigned nb = __float_as_uint(g_bnorm[b][tid]);
        bkey[tid] = ((unsigned long long)nb << 32) | (unsigned)(0xFFFFFFFFu - r);
    }
    __syncwarp();
    if (tid < nc) {
        unsigned long long me = bkey[tid];
        int rank = 0;
        for (int t = 0; t < nc; t++) rank += (bkey[t] > me);
        if (rank < remaining) {
            int r = (int)(0xFFFFFFFFu - (unsigned)(me & 0xFFFFFFFFull));
            g_topidx[b * KTOP + C1 + rank] = r;
        }
    }
}

// ---------------- attention on the top-k set, scattered store ----------------
__global__ __launch_bounds__(256) void attn_kernel(float* __restrict__ out) {
    constexpr int QT = 16;
    constexpr int NT = 26;
    constexpr int CW = 416;
    __shared__ float q_s[QT][132];
    __shared__ float kv_s[QT][132];
    __shared__ float S_s[QT][CW];
    __shared__ int qidx[QT];

    const int b = blockIdx.x / NT;
    const int qt = blockIdx.x % NT;
    const int q0 = qt * QT;
    const int tid = threadIdx.x;
    const float scale = 0.08838834764831845f;

    if (tid < QT) {
        int r = q0 + tid;
        qidx[tid] = (r < KTOP) ? g_topidx[b * KTOP + r] : -1;
    }
    __syncthreads();
    for (int u = tid; u < QT * DD; u += 256) {
        int i = u >> 7, d = u & 127;
        int rg = qidx[i];
        q_s[i][d] = (rg >= 0) ? g_q[((size_t)b * TT + rg) * DD + d] : 0.f;
    }

    const int i = tid >> 4;
    const int jj = tid & 15;

    for (int jt = 0; jt < NT; jt++) {
        __syncthreads();
        for (int u = tid; u < QT * DD; u += 256) {
            int j2 = u >> 7, d = u & 127;
            int j = jt * QT + j2;
            kv_s[j2][d] = (j < KTOP) ? g_ktop[((size_t)b * KTOP + j) * DD + d] : 0.f;
        }
        __syncthreads();
        float s = 0.f;
#pragma unroll
        for (int d4 = 0; d4 < DD; d4 += 4) {
            float4 qa = *(const float4*)&q_s[i][d4];
            float4 kb = *(const float4*)&kv_s[jj][d4];
            s += qa.x * kb.x + qa.y * kb.y + qa.z * kb.z + qa.w * kb.w;
        }
        int j = jt * QT + jj;
        S_s[i][j] = (j < KTOP) ? s * scale : -1e30f;
    }
    __syncthreads();

    {
        int l = tid & 15;
        float m = -1e30f;
        for (int cc = l; cc < CW; cc += 16) m = fmaxf(m, S_s[i][cc]);
#pragma unroll
        for (int o = 8; o; o >>= 1) m = fmaxf(m, __shfl_xor_sync(0xffffffffu, m, o));
        float sum = 0.f;
        for (int cc = l; cc < CW; cc += 16) {
            float e = __expf(S_s[i][cc] - m);
            S_s[i][cc] = e;
            sum += e;
        }
#pragma unroll
        for (int o = 8; o; o >>= 1) sum += __shfl_xor_sync(0xffffffffu, sum, o);
        float inv = 1.f / sum;
        for (int cc = l; cc < CW; cc += 16) S_s[i][cc] *= inv;
    }

    float acc[8] = {0.f, 0.f, 0.f, 0.f, 0.f, 0.f, 0.f, 0.f};
    const int d0 = (tid & 15) * 8;
    for (int jt = 0; jt < NT; jt++) {
        __syncthreads();
        for (int u = tid; u < QT * DD; u += 256) {
            int j2 = u >> 7, d = u & 127;
            int j = jt * QT + j2;
            kv_s[j2][d] = (j < KTOP) ? g_vtop[((size_t)b * KTOP + j) * DD + d] : 0.f;
        }
        __syncthreads();
#pragma unroll
        for (int j2 = 0; j2 < QT; j2++) {
            float p = S_s[i][jt * QT + j2];
            float4 v0 = *(const float4*)&kv_s[j2][d0];
            float4 v1 = *(const float4*)&kv_s[j2][d0 + 4];
            acc[0] += p * v0.x;
            acc[1] += p * v0.y;
            acc[2] += p * v0.z;
            acc[3] += p * v0.w;
            acc[4] += p * v1.x;
            acc[5] += p * v1.y;
            acc[6] += p * v1.z;
            acc[7] += p * v1.w;
        }
    }
    int r = q0 + i;
    if (r < KTOP) {
        int rg = g_topidx[b * KTOP + r];
        float* op = out + ((size_t)b * TT + rg) * DD + d0;
        *(float4*)op = make_float4(acc[0], acc[1], acc[2], acc[3]);
        *(float4*)(op + 4) = make_float4(acc[4], acc[5], acc[6], acc[7]);
    }
}

// ---------------- launch ----------------
extern "C" void kernel_launch(void* const* d_in, const int* in_sizes, int n_in,
                              void* d_out, int out_size) {
    (void)in_sizes;
    (void)n_in;
    (void)out_size;
    const float* index = (const float*)d_in[0];
    const float* Wq = (const float*)d_in[1];
    const float* Wk = (const float*)d_in[2];
    const float* Wv = (const float*)d_in[3];
    float* out = (float*)d_out;

    cudaFuncSetAttribute(gemm_mma<false>,
                         cudaFuncAttributeMaxDynamicSharedMemorySize, S_TOTAL);
    cudaFuncSetAttribute(gemm_mma<true>,
                         cudaFuncAttributeMaxDynamicSharedMemorySize, S_TOTAL);

    zero_kernel<<<512, 256>>>((float4*)out, BB * TT * DD / 4);          // 1
    wprep_kernel<<<dim3(EE / 32, DD / 32), 256>>>(Wq, Wk, Wv);          // 2
    gemm_mma<false><<<(BB * TT) / 128, 512, S_TOTAL>>>(index);          // 3
    topk_select<<<BB, 1024>>>();                                        // 4 (profiled)
    refine_kernel<<<dim3(NCAND, BB), 256>>>(index, Wq);                 // 5
    finalize_kernel<<<BB, 32>>>();                                      // 6
    gemm_mma<true><<<dim3(16, 2, NKV), 512, S_TOTAL>>>(index);          // 7
    reduce_kv<<<512, 256>>>();                                          // 8
    attn_kernel<<<BB * 26, 256>>>(out);                                 // 9
}